// round 2
// baseline (speedup 1.0000x reference)
#include <cuda_runtime.h>
#include <cuda_bf16.h>

#define NN 100000
#define EE 1600000

// ---------------- scratch (device globals; no allocation) ----------------
__device__ float g_feat1[NN * 128];   // layer1 features [N][H=4][D=32]
__device__ float g_el1[NN * 4];
__device__ float g_er1[NN * 4];
__device__ float g_h[NN * 32];        // mid features after mean+relu
__device__ float g_feat2[NN * 16];
__device__ float g_el2[NN];
__device__ float g_er2[NN];
__device__ int   g_rowptr[NN + 1];
__device__ int   g_cursor[NN];
__device__ int   g_csrsrc[EE];
__device__ int   g_bsum[256];

// ---------------- f32x2 packed FMA (Blackwell) ----------------
__device__ __forceinline__ unsigned long long ffma2(unsigned long long a,
                                                    unsigned long long b,
                                                    unsigned long long c) {
    unsigned long long d;
    asm("fma.rn.f32x2 %0, %1, %2, %3;" : "=l"(d) : "l"(a), "l"(b), "l"(c));
    return d;
}

// ---------------- GEMM1: feat1 = x @ W1  (N x 128 x 128) ----------------
__global__ void __launch_bounds__(256) gemm1_kernel(const float* __restrict__ x,
                                                    const float* __restrict__ W) {
    __shared__ float As[16][128];   // [k][row]
    __shared__ float Bs[16][128];   // [k][col]
    int tid = threadIdx.x;
    int row0 = blockIdx.x * 128;
    int tr = tid >> 4;       // 0..15 row group (8 rows each)
    int tc = tid & 15;       // 0..15 col group

    unsigned long long acc[8][4];
#pragma unroll
    for (int i = 0; i < 8; i++)
#pragma unroll
        for (int j = 0; j < 4; j++) acc[i][j] = 0ULL;

    for (int k0 = 0; k0 < 128; k0 += 16) {
#pragma unroll
        for (int q = 0; q < 2; q++) {
            int f = tid * 2 + q;                 // 0..511
            // A tile: 128 rows x 16 k
            int r = f >> 2, c4 = (f & 3) << 2;
            int grow = row0 + r;
            float4 v = make_float4(0.f, 0.f, 0.f, 0.f);
            if (grow < NN) v = *(const float4*)&x[grow * 128 + k0 + c4];
            As[c4 + 0][r] = v.x; As[c4 + 1][r] = v.y;
            As[c4 + 2][r] = v.z; As[c4 + 3][r] = v.w;
            // B tile: 16 k x 128 cols
            int kr = f >> 5, c8 = (f & 31) << 2;
            float4 wv = *(const float4*)&W[(k0 + kr) * 128 + c8];
            *(float4*)&Bs[kr][c8] = wv;
        }
        __syncthreads();
#pragma unroll
        for (int kk = 0; kk < 16; kk++) {
            unsigned long long b2[4];
#pragma unroll
            for (int j = 0; j < 4; j++)
                b2[j] = *(const unsigned long long*)&Bs[kk][tc * 2 + j * 32];
#pragma unroll
            for (int i = 0; i < 8; i++) {
                float a = As[kk][tr * 8 + i];
                unsigned long long a2;
                asm("mov.b64 %0, {%1, %2};" : "=l"(a2) : "f"(a), "f"(a));
#pragma unroll
                for (int j = 0; j < 4; j++) acc[i][j] = ffma2(a2, b2[j], acc[i][j]);
            }
        }
        __syncthreads();
    }
#pragma unroll
    for (int i = 0; i < 8; i++) {
        int grow = row0 + tr * 8 + i;
        if (grow < NN) {
#pragma unroll
            for (int j = 0; j < 4; j++)
                *(unsigned long long*)&g_feat1[grow * 128 + tc * 2 + j * 32] = acc[i][j];
        }
    }
}

// ---------------- attention coefficients layer 1 ----------------
__global__ void coef1_kernel(const float* __restrict__ al1, const float* __restrict__ ar1) {
    int n = blockIdx.x;
    int t = threadIdx.x;
    int h = t >> 5, d = t & 31;
    float v = g_feat1[n * 128 + t];
    float pe = v * al1[t];
    float pr = v * ar1[t];
#pragma unroll
    for (int o = 16; o; o >>= 1) {
        pe += __shfl_xor_sync(0xffffffffu, pe, o);
        pr += __shfl_xor_sync(0xffffffffu, pr, o);
    }
    if (d == 0) { g_el1[n * 4 + h] = pe; g_er1[n * 4 + h] = pr; }
}

// ---------------- CSR build ----------------
__global__ void zero_cursor_kernel() {
    int i = blockIdx.x * 256 + threadIdx.x;
    if (i < NN) g_cursor[i] = 0;
}
__global__ void hist_kernel(const int* __restrict__ dst) {
    int e = blockIdx.x * 256 + threadIdx.x;
    if (e < EE) atomicAdd(&g_cursor[dst[e]], 1);
}
__global__ void scan1_kernel() {   // 256 blocks x 256 threads, 2 elems/thread
    __shared__ int sh[256];
    int b = blockIdx.x, t = threadIdx.x;
    int i0 = (b * 256 + t) * 2;
    int s = 0;
    if (i0 < NN)     s += g_cursor[i0];
    if (i0 + 1 < NN) s += g_cursor[i0 + 1];
    sh[t] = s; __syncthreads();
    for (int o = 128; o; o >>= 1) { if (t < o) sh[t] += sh[t + o]; __syncthreads(); }
    if (t == 0) g_bsum[b] = sh[0];
}
__global__ void scan2_kernel() {   // 1 block, exclusive scan of 256 block sums
    __shared__ int sh[256];
    int t = threadIdx.x;
    int mine = g_bsum[t];
    sh[t] = mine; __syncthreads();
    for (int o = 1; o < 256; o <<= 1) {
        int v = (t >= o) ? sh[t - o] : 0;
        __syncthreads();
        sh[t] += v;
        __syncthreads();
    }
    g_bsum[t] = sh[t] - mine;                // exclusive
    if (t == 255) g_rowptr[NN] = sh[255];    // total == EE
}
__global__ void scan3_kernel() {
    __shared__ int sh[256];
    int b = blockIdx.x, t = threadIdx.x;
    int i0 = (b * 256 + t) * 2;
    int c0 = (i0 < NN) ? g_cursor[i0] : 0;
    int c1 = (i0 + 1 < NN) ? g_cursor[i0 + 1] : 0;
    int local = c0 + c1;
    sh[t] = local; __syncthreads();
    for (int o = 1; o < 256; o <<= 1) {
        int v = (t >= o) ? sh[t - o] : 0;
        __syncthreads();
        sh[t] += v;
        __syncthreads();
    }
    int off = g_bsum[b] + sh[t] - local;
    if (i0 < NN)     { g_rowptr[i0] = off;          g_cursor[i0] = off; }
    if (i0 + 1 < NN) { g_rowptr[i0 + 1] = off + c0; g_cursor[i0 + 1] = off + c0; }
}
__global__ void scatter_kernel(const int* __restrict__ src, const int* __restrict__ dst) {
    int e = blockIdx.x * 256 + threadIdx.x;
    if (e < EE) {
        int d = dst[e];
        int slot = atomicAdd(&g_cursor[d], 1);
        g_csrsrc[slot] = src[e];
    }
}

// ---------------- layer 1 node aggregation (softmax + SpMM + mean + relu) --
__global__ void node1_kernel(const float* __restrict__ b1) {
    int n = blockIdx.x;
    int t = threadIdx.x;
    int h = t >> 5, d = t & 31;
    int beg = g_rowptr[n], end = g_rowptr[n + 1];
    int deg = end - beg;
    __shared__ int   sh_src[128];
    __shared__ float sh_w[4][128];
    __shared__ float sh_v[4][32];

    float er_nh = g_er1[n * 4 + h];

    // pass A: segment max (lane-split)
    float m = -1e30f;
    for (int c0 = 0; c0 < deg; c0 += 128) {
        int cnt = min(deg - c0, 128);
        __syncthreads();
        if (t < cnt) sh_src[t] = g_csrsrc[beg + c0 + t];
        __syncthreads();
        for (int j = d; j < cnt; j += 32) {
            int s = sh_src[j];
            float e = g_el1[s * 4 + h] + er_nh;
            e = (e > 0.f) ? e : 0.2f * e;
            m = fmaxf(m, e);
        }
    }
#pragma unroll
    for (int o = 16; o; o >>= 1) m = fmaxf(m, __shfl_xor_sync(0xffffffffu, m, o));

    // pass B: weights + denom + weighted feature gather
    float denom = 0.f, acc = 0.f;
    for (int c0 = 0; c0 < deg; c0 += 128) {
        int cnt = min(deg - c0, 128);
        __syncthreads();
        if (t < cnt) sh_src[t] = g_csrsrc[beg + c0 + t];
        __syncthreads();
        for (int j = d; j < cnt; j += 32) {
            int s = sh_src[j];
            float e = g_el1[s * 4 + h] + er_nh;
            e = (e > 0.f) ? e : 0.2f * e;
            float w = __expf(e - m);
            denom += w;
            sh_w[h][j] = w;
        }
        __syncwarp();
        int j = 0;
        for (; j + 4 <= cnt; j += 4) {
            float w0 = sh_w[h][j],     w1 = sh_w[h][j + 1];
            float w2 = sh_w[h][j + 2], w3 = sh_w[h][j + 3];
            int s0 = sh_src[j],     s1 = sh_src[j + 1];
            int s2 = sh_src[j + 2], s3 = sh_src[j + 3];
            float f0 = g_feat1[s0 * 128 + h * 32 + d];
            float f1 = g_feat1[s1 * 128 + h * 32 + d];
            float f2 = g_feat1[s2 * 128 + h * 32 + d];
            float f3 = g_feat1[s3 * 128 + h * 32 + d];
            acc = fmaf(w0, f0, acc); acc = fmaf(w1, f1, acc);
            acc = fmaf(w2, f2, acc); acc = fmaf(w3, f3, acc);
        }
        for (; j < cnt; j++)
            acc = fmaf(sh_w[h][j], g_feat1[sh_src[j] * 128 + h * 32 + d], acc);
    }
#pragma unroll
    for (int o = 16; o; o >>= 1) denom += __shfl_xor_sync(0xffffffffu, denom, o);

    float dsafe = (denom == 0.f) ? 1.f : denom;
    float val = acc / dsafe + b1[h * 32 + d];
    sh_v[h][d] = val;
    __syncthreads();
    if (h == 0) {
        float mn = 0.25f * (sh_v[0][d] + sh_v[1][d] + sh_v[2][d] + sh_v[3][d]);
        g_h[n * 32 + d] = fmaxf(mn, 0.f);
    }
}

// ---------------- GEMM2 + coefficients layer 2 ----------------
// block 256 = 8 warps; each warp handles 2 nodes (16 lanes per node).
__global__ void gemm2_kernel(const float* __restrict__ W2,
                             const float* __restrict__ al2,
                             const float* __restrict__ ar2) {
    __shared__ float sW[32 * 16];
    int t = threadIdx.x;
    for (int i = t; i < 512; i += 256) sW[i] = W2[i];   // FIX: all 512 elements
    __syncthreads();
    int warp = t >> 5, lane = t & 31;
    int g = lane >> 4, c = lane & 15;
    int n = (blockIdx.x * 8 + warp) * 2 + g;
    if (n >= NN) return;
    const float* hrow = g_h + n * 32;
    float acc = 0.f;
#pragma unroll
    for (int k = 0; k < 32; k++) acc = fmaf(hrow[k], sW[k * 16 + c], acc);
    g_feat2[n * 16 + c] = acc;
    float pe = acc * al2[c];
    float pr = acc * ar2[c];
#pragma unroll
    for (int o = 8; o; o >>= 1) {
        pe += __shfl_xor_sync(0xffffffffu, pe, o);
        pr += __shfl_xor_sync(0xffffffffu, pr, o);
    }
    if (c == 0) { g_el2[n] = pe; g_er2[n] = pr; }
}

// ---------------- layer 2 node aggregation ----------------
__global__ void node2_kernel(const float* __restrict__ b2, float* __restrict__ out) {
    int warp = threadIdx.x >> 5;
    int lane = threadIdx.x & 31;
    int n = blockIdx.x * 4 + warp;
    if (n >= NN) return;
    int beg = g_rowptr[n], end = g_rowptr[n + 1];
    int deg = end - beg;
    float er_n = g_er2[n];
    int p = lane >> 4, d = lane & 15;

    // pass A: max
    float m = -1e30f;
    for (int c0 = 0; c0 < deg; c0 += 32) {
        int cnt = min(deg - c0, 32);
        if (lane < cnt) {
            int s = g_csrsrc[beg + c0 + lane];
            float e = g_el2[s] + er_n;
            e = (e > 0.f) ? e : 0.2f * e;
            m = fmaxf(m, e);
        }
    }
#pragma unroll
    for (int o = 16; o; o >>= 1) m = fmaxf(m, __shfl_xor_sync(0xffffffffu, m, o));

    // pass B
    float denom = 0.f, acc = 0.f;
    for (int c0 = 0; c0 < deg; c0 += 32) {
        int cnt = min(deg - c0, 32);
        int s = 0; float w = 0.f;
        if (lane < cnt) {
            s = g_csrsrc[beg + c0 + lane];
            float e = g_el2[s] + er_n;
            e = (e > 0.f) ? e : 0.2f * e;
            w = __expf(e - m);
            denom += w;
        }
        for (int j2 = 0; j2 < cnt; j2 += 2) {
            int j = j2 + p;
            int jj = (j < cnt) ? j : 0;
            float wj = __shfl_sync(0xffffffffu, w, jj);
            int   sj = __shfl_sync(0xffffffffu, s, jj);
            if (j < cnt) acc = fmaf(wj, g_feat2[sj * 16 + d], acc);
        }
    }
#pragma unroll
    for (int o = 16; o; o >>= 1) denom += __shfl_xor_sync(0xffffffffu, denom, o);
    acc += __shfl_down_sync(0xffffffffu, acc, 16);
    float dsafe = (denom == 0.f) ? 1.f : denom;
    if (lane < 16) out[n * 16 + lane] = acc / dsafe + b2[lane];
}

// ---------------- launch ----------------
extern "C" void kernel_launch(void* const* d_in, const int* in_sizes, int n_in,
                              void* d_out, int out_size) {
    const float* x   = (const float*)d_in[0];
    const int*   src = (const int*)  d_in[1];
    const int*   dst = (const int*)  d_in[2];
    const float* W1  = (const float*)d_in[3];
    const float* al1 = (const float*)d_in[4];
    const float* ar1 = (const float*)d_in[5];
    const float* b1  = (const float*)d_in[6];
    const float* W2  = (const float*)d_in[7];
    const float* al2 = (const float*)d_in[8];
    const float* ar2 = (const float*)d_in[9];
    const float* b2  = (const float*)d_in[10];
    float* out = (float*)d_out;

    // CSR build (independent of GEMM; serial stream order is fine)
    zero_cursor_kernel<<<(NN + 255) / 256, 256>>>();
    hist_kernel<<<(EE + 255) / 256, 256>>>(dst);
    scan1_kernel<<<256, 256>>>();
    scan2_kernel<<<1, 256>>>();
    scan3_kernel<<<256, 256>>>();
    scatter_kernel<<<(EE + 255) / 256, 256>>>(src, dst);

    // layer 1
    gemm1_kernel<<<(NN + 127) / 128, 256>>>(x, W1);
    coef1_kernel<<<NN, 128>>>(al1, ar1);
    node1_kernel<<<NN, 128>>>(b1);

    // layer 2
    gemm2_kernel<<<(NN + 15) / 16, 256>>>(W2, al2, ar2);
    node2_kernel<<<(NN + 3) / 4, 128>>>(b2, out);
}

// round 8
// speedup vs baseline: 1.1810x; 1.1810x over previous
#include <cuda_runtime.h>
#include <cuda_bf16.h>

#define NN 100000
#define EE 1600000
#define SCAN_NB 196   // ceil(NN/512)

// ---------------- scratch (device globals; no allocation) ----------------
__device__ float g_feat1[NN * 128];   // layer1 features [N][H=4][D=32]
__device__ float g_el1[NN * 4];
__device__ float g_er1[NN * 4];
__device__ float g_h[NN * 32];        // mid features after mean+relu
__device__ float g_feat2[NN * 16];
__device__ float g_el2[NN];
__device__ float g_er2[NN];
__device__ int   g_rowptr[NN + 1];
__device__ int   g_cursor[NN];
__device__ int   g_csrsrc[EE];
__device__ unsigned long long g_desc[SCAN_NB];  // lookback: flag<<32 | value
__device__ int   g_scanctr;

// ---------------- f32x2 packed FMA (Blackwell) ----------------
__device__ __forceinline__ unsigned long long ffma2(unsigned long long a,
                                                    unsigned long long b,
                                                    unsigned long long c) {
    unsigned long long d;
    asm("fma.rn.f32x2 %0, %1, %2, %3;" : "=l"(d) : "l"(a), "l"(b), "l"(c));
    return d;
}

// ---------------- init: cursors, scan descriptors, rowptr[NN] -------------
__global__ void zero_kernel() {
    int i = blockIdx.x * 256 + threadIdx.x;
    if (i < NN) g_cursor[i] = 0;
    if (i < SCAN_NB) g_desc[i] = 0ULL;
    if (i == 0) { g_scanctr = 0; g_rowptr[NN] = EE; }
}

// ---------------- histogram of dst ----------------
__global__ void hist_kernel(const int* __restrict__ dst) {
    int e = blockIdx.x * 256 + threadIdx.x;
    if (e < EE) atomicAdd(&g_cursor[dst[e]], 1);
}

// ---------------- single-pass exclusive scan (decoupled lookback) ---------
// 256 threads, 512 elements per block. Writes g_rowptr and resets g_cursor
// to the row start (scatter cursor).
__global__ void __launch_bounds__(256) scan_kernel() {
    __shared__ int sh[256];
    __shared__ int s_bid;
    __shared__ int s_prefix;
    int t = threadIdx.x;
    if (t == 0) s_bid = atomicAdd(&g_scanctr, 1);
    __syncthreads();
    int b = s_bid;
    int i0 = b * 512 + 2 * t;
    int c0 = (i0 < NN) ? g_cursor[i0] : 0;
    int c1 = (i0 + 1 < NN) ? g_cursor[i0 + 1] : 0;
    int local = c0 + c1;
    sh[t] = local;
    __syncthreads();
    for (int o = 1; o < 256; o <<= 1) {
        int v = (t >= o) ? sh[t - o] : 0;
        __syncthreads();
        sh[t] += v;
        __syncthreads();
    }
    int total = sh[255];
    if (t == 0) {
        if (b == 0) {
            *(volatile unsigned long long*)&g_desc[0] =
                (2ULL << 32) | (unsigned long long)(unsigned)total;
            s_prefix = 0;
        } else {
            *(volatile unsigned long long*)&g_desc[b] =
                (1ULL << 32) | (unsigned long long)(unsigned)total;
            int prefix = 0;
            int j = b - 1;
            while (true) {
                unsigned long long dsc;
                do { dsc = *(volatile unsigned long long*)&g_desc[j]; } while ((dsc >> 32) == 0ULL);
                prefix += (int)(unsigned)dsc;
                if ((dsc >> 32) == 2ULL) break;
                j--;
            }
            *(volatile unsigned long long*)&g_desc[b] =
                (2ULL << 32) | (unsigned long long)(unsigned)(prefix + total);
            s_prefix = prefix;
        }
    }
    __syncthreads();
    int off = s_prefix + sh[t] - local;
    if (i0 < NN)     { g_rowptr[i0] = off;          g_cursor[i0] = off; }
    if (i0 + 1 < NN) { g_rowptr[i0 + 1] = off + c0; g_cursor[i0 + 1] = off + c0; }
}

// ---------------- scatter edges into CSR ----------------
__global__ void scatter_kernel(const int* __restrict__ src, const int* __restrict__ dst) {
    int e = blockIdx.x * 256 + threadIdx.x;
    if (e < EE) {
        int d = dst[e];
        int slot = atomicAdd(&g_cursor[d], 1);
        g_csrsrc[slot] = src[e];
    }
}

// ---------------- GEMM1 + fused attention coefficients -------------------
// feat1 = x @ W1 (N x 128 x 128), then el/er = per-head dots with al1/ar1
// computed in the epilogue via a shared-memory 16-lane reduction.
__global__ void __launch_bounds__(256) gemm1_kernel(const float* __restrict__ x,
                                                    const float* __restrict__ W,
                                                    const float* __restrict__ al1,
                                                    const float* __restrict__ ar1) {
    __shared__ float As[16][128];   // [k][row]
    __shared__ float Bs[16][128];   // [k][col]
    __shared__ float sRed[2][16][129];  // coef reduction, bank-conflict-free
    int tid = threadIdx.x;
    int row0 = blockIdx.x * 128;
    int tr = tid >> 4;       // 0..15 row group (8 rows each)
    int tc = tid & 15;       // 0..15 col group

    unsigned long long acc[8][4];
#pragma unroll
    for (int i = 0; i < 8; i++)
#pragma unroll
        for (int j = 0; j < 4; j++) acc[i][j] = 0ULL;

    for (int k0 = 0; k0 < 128; k0 += 16) {
#pragma unroll
        for (int q = 0; q < 2; q++) {
            int f = tid * 2 + q;                 // 0..511
            int r = f >> 2, c4 = (f & 3) << 2;
            int grow = row0 + r;
            float4 v = make_float4(0.f, 0.f, 0.f, 0.f);
            if (grow < NN) v = *(const float4*)&x[grow * 128 + k0 + c4];
            As[c4 + 0][r] = v.x; As[c4 + 1][r] = v.y;
            As[c4 + 2][r] = v.z; As[c4 + 3][r] = v.w;
            int kr = f >> 5, c8 = (f & 31) << 2;
            float4 wv = *(const float4*)&W[(k0 + kr) * 128 + c8];
            *(float4*)&Bs[kr][c8] = wv;
        }
        __syncthreads();
#pragma unroll
        for (int kk = 0; kk < 16; kk++) {
            unsigned long long b2[4];
#pragma unroll
            for (int j = 0; j < 4; j++)
                b2[j] = *(const unsigned long long*)&Bs[kk][tc * 2 + j * 32];
#pragma unroll
            for (int i = 0; i < 8; i++) {
                float a = As[kk][tr * 8 + i];
                unsigned long long a2;
                asm("mov.b64 %0, {%1, %2};" : "=l"(a2) : "f"(a), "f"(a));
#pragma unroll
                for (int j = 0; j < 4; j++) acc[i][j] = ffma2(a2, b2[j], acc[i][j]);
            }
        }
        __syncthreads();
    }
    // store features
#pragma unroll
    for (int i = 0; i < 8; i++) {
        int grow = row0 + tr * 8 + i;
        if (grow < NN) {
#pragma unroll
            for (int j = 0; j < 4; j++)
                *(unsigned long long*)&g_feat1[grow * 128 + tc * 2 + j * 32] = acc[i][j];
        }
    }
    // fused coefficients: per head j, partial dots then 16-lane smem reduce
#pragma unroll
    for (int j = 0; j < 4; j++) {
        float alo = al1[j * 32 + tc * 2], ahi = al1[j * 32 + tc * 2 + 1];
        float rlo = ar1[j * 32 + tc * 2], rhi = ar1[j * 32 + tc * 2 + 1];
        __syncthreads();
#pragma unroll
        for (int i = 0; i < 8; i++) {
            float lo, hi;
            asm("mov.b64 {%0, %1}, %2;" : "=f"(lo), "=f"(hi) : "l"(acc[i][j]));
            sRed[0][tc][tr * 8 + i] = lo * alo + hi * ahi;
            sRed[1][tc][tr * 8 + i] = lo * rlo + hi * rhi;
        }
        __syncthreads();
        if (tid < 128) {
            int row = tid;
            float se = 0.f, sr = 0.f;
#pragma unroll
            for (int c = 0; c < 16; c++) {
                se += sRed[0][c][row];
                sr += sRed[1][c][row];
            }
            int grow = row0 + row;
            if (grow < NN) {
                g_el1[grow * 4 + j] = se;
                g_er1[grow * 4 + j] = sr;
            }
        }
    }
}

// ---------------- layer 1 node aggregation (softmax + SpMM + mean + relu) --
// Single pass, no segment max (exp(e)/sum(exp(e)) == softmax exactly).
// block 128 = one dst node; warp h = head h; lane d = feature.
__global__ void __launch_bounds__(128) node1_kernel(const float* __restrict__ b1) {
    int n = blockIdx.x;
    int t = threadIdx.x;
    int h = t >> 5, d = t & 31;
    int beg = g_rowptr[n], end = g_rowptr[n + 1];
    int deg = end - beg;
    __shared__ int   sh_src[128];
    __shared__ float sh_w[4][128];
    __shared__ float sh_v[4][32];

    float4 ern = *(const float4*)&g_er1[n * 4];   // broadcast

    float denom = 0.f, acc = 0.f;
    for (int c0 = 0; c0 < deg; c0 += 128) {
        int cnt = min(deg - c0, 128);
        __syncthreads();
        if (t < cnt) {
            int s = g_csrsrc[beg + c0 + t];
            sh_src[t] = s;
            float4 el = *(const float4*)&g_el1[s * 4];
            float e0 = el.x + ern.x; e0 = (e0 > 0.f) ? e0 : 0.2f * e0;
            float e1 = el.y + ern.y; e1 = (e1 > 0.f) ? e1 : 0.2f * e1;
            float e2 = el.z + ern.z; e2 = (e2 > 0.f) ? e2 : 0.2f * e2;
            float e3 = el.w + ern.w; e3 = (e3 > 0.f) ? e3 : 0.2f * e3;
            sh_w[0][t] = __expf(e0);
            sh_w[1][t] = __expf(e1);
            sh_w[2][t] = __expf(e2);
            sh_w[3][t] = __expf(e3);
        }
        __syncthreads();
        // per-head denom partials (lane-split)
        for (int j = d; j < cnt; j += 32) denom += sh_w[h][j];
        // weighted feature gather
        int j = 0;
        for (; j + 4 <= cnt; j += 4) {
            float w0 = sh_w[h][j],     w1 = sh_w[h][j + 1];
            float w2 = sh_w[h][j + 2], w3 = sh_w[h][j + 3];
            int s0 = sh_src[j],     s1 = sh_src[j + 1];
            int s2 = sh_src[j + 2], s3 = sh_src[j + 3];
            float f0 = g_feat1[s0 * 128 + h * 32 + d];
            float f1 = g_feat1[s1 * 128 + h * 32 + d];
            float f2 = g_feat1[s2 * 128 + h * 32 + d];
            float f3 = g_feat1[s3 * 128 + h * 32 + d];
            acc = fmaf(w0, f0, acc); acc = fmaf(w1, f1, acc);
            acc = fmaf(w2, f2, acc); acc = fmaf(w3, f3, acc);
        }
        for (; j < cnt; j++)
            acc = fmaf(sh_w[h][j], g_feat1[sh_src[j] * 128 + h * 32 + d], acc);
    }
#pragma unroll
    for (int o = 16; o; o >>= 1) denom += __shfl_xor_sync(0xffffffffu, denom, o);

    float dsafe = (denom == 0.f) ? 1.f : denom;
    float val = acc / dsafe + b1[h * 32 + d];
    sh_v[h][d] = val;
    __syncthreads();
    if (h == 0) {
        float mn = 0.25f * (sh_v[0][d] + sh_v[1][d] + sh_v[2][d] + sh_v[3][d]);
        g_h[n * 32 + d] = fmaxf(mn, 0.f);
    }
}

// ---------------- GEMM2 + coefficients layer 2 ----------------
__global__ void gemm2_kernel(const float* __restrict__ W2,
                             const float* __restrict__ al2,
                             const float* __restrict__ ar2) {
    __shared__ float sW[32 * 16];
    int t = threadIdx.x;
    for (int i = t; i < 512; i += 256) sW[i] = W2[i];
    __syncthreads();
    int warp = t >> 5, lane = t & 31;
    int g = lane >> 4, c = lane & 15;
    int n = (blockIdx.x * 8 + warp) * 2 + g;
    if (n >= NN) return;
    const float* hrow = g_h + n * 32;
    float acc = 0.f;
#pragma unroll
    for (int k = 0; k < 32; k++) acc = fmaf(hrow[k], sW[k * 16 + c], acc);
    g_feat2[n * 16 + c] = acc;
    float pe = acc * al2[c];
    float pr = acc * ar2[c];
#pragma unroll
    for (int o = 8; o; o >>= 1) {
        pe += __shfl_xor_sync(0xffffffffu, pe, o);
        pr += __shfl_xor_sync(0xffffffffu, pr, o);
    }
    if (c == 0) { g_el2[n] = pe; g_er2[n] = pr; }
}

// ---------------- layer 2 node aggregation (single pass, no max) ----------
__global__ void node2_kernel(const float* __restrict__ b2, float* __restrict__ out) {
    int warp = threadIdx.x >> 5;
    int lane = threadIdx.x & 31;
    int n = blockIdx.x * 4 + warp;
    if (n >= NN) return;
    int beg = g_rowptr[n], end = g_rowptr[n + 1];
    int deg = end - beg;
    float er_n = g_er2[n];
    int p = lane >> 4, d = lane & 15;

    float denom = 0.f, acc = 0.f;
    for (int c0 = 0; c0 < deg; c0 += 32) {
        int cnt = min(deg - c0, 32);
        int s = 0; float w = 0.f;
        if (lane < cnt) {
            s = g_csrsrc[beg + c0 + lane];
            float e = g_el2[s] + er_n;
            e = (e > 0.f) ? e : 0.2f * e;
            w = __expf(e);
            denom += w;
        }
        for (int j2 = 0; j2 < cnt; j2 += 2) {
            int j = j2 + p;
            int jj = (j < cnt) ? j : 0;
            float wj = __shfl_sync(0xffffffffu, w, jj);
            int   sj = __shfl_sync(0xffffffffu, s, jj);
            if (j < cnt) acc = fmaf(wj, g_feat2[sj * 16 + d], acc);
        }
    }
#pragma unroll
    for (int o = 16; o; o >>= 1) denom += __shfl_xor_sync(0xffffffffu, denom, o);
    acc += __shfl_down_sync(0xffffffffu, acc, 16);
    float dsafe = (denom == 0.f) ? 1.f : denom;
    if (lane < 16) out[n * 16 + lane] = acc / dsafe + b2[lane];
}

// ---------------- launch ----------------
// Order matters for ncu (-s 5 -c 1): launch index 5 == node1_kernel.
extern "C" void kernel_launch(void* const* d_in, const int* in_sizes, int n_in,
                              void* d_out, int out_size) {
    const float* x   = (const float*)d_in[0];
    const int*   src = (const int*)  d_in[1];
    const int*   dst = (const int*)  d_in[2];
    const float* W1  = (const float*)d_in[3];
    const float* al1 = (const float*)d_in[4];
    const float* ar1 = (const float*)d_in[5];
    const float* b1  = (const float*)d_in[6];
    const float* W2  = (const float*)d_in[7];
    const float* al2 = (const float*)d_in[8];
    const float* ar2 = (const float*)d_in[9];
    const float* b2  = (const float*)d_in[10];
    float* out = (float*)d_out;

    zero_kernel<<<(NN + 255) / 256, 256>>>();                 // 0
    hist_kernel<<<(EE + 255) / 256, 256>>>(dst);              // 1
    scan_kernel<<<SCAN_NB, 256>>>();                          // 2
    scatter_kernel<<<(EE + 255) / 256, 256>>>(src, dst);      // 3
    gemm1_kernel<<<(NN + 127) / 128, 256>>>(x, W1, al1, ar1); // 4
    node1_kernel<<<NN, 128>>>(b1);                            // 5  <-- profiled
    gemm2_kernel<<<(NN + 15) / 16, 256>>>(W2, al2, ar2);      // 6
    node2_kernel<<<(NN + 3) / 4, 128>>>(b2, out);             // 7
}